// round 12
// baseline (speedup 1.0000x reference)
#include <cuda_runtime.h>
#include <cuda_bf16.h>

#define NS      65536
#define NRES    16
#define NOSC    16
#define NCPD    16
#define WIN     2048
#define FRAMES  512
#define DEFF    256
#define RE      32            // NRES*NEXPR
#define ORE     512           // NOSC*NRES*NEXPR
#define OB      65536         // out offset: before_upsample
#define OC      73728         // out offset: cs
#define DELTA   (10.0f/65535.0f)
#define HEAD    3072          // direct-FIR head length (>= 2057, mult of 1024)
#define RESN    4096          // samples of d_res materialized (all gfir ever reads)

// ----------------------------- device scratch --------------------------------
__device__ float d_xd[ORE], d_om[ORE], d_phi[ORE], d_aa[ORE], d_am[ORE];
__device__ float d_sc[ORE], d_sn[ORE], d_ed[ORE];   // per-mode step cos/sin, env step
__device__ int   d_nco[ORE];
__device__ int   d_Lg[RE];
__device__ float d_routed[NRES*FRAMES];
__device__ float d_imp[NCPD*WIN];
__device__ float d_dsm[2*DEFF];
__device__ float d_m0[NRES], d_m1[NRES], d_ga[NRES];
__device__ float d_res[RE*RESN];   // un-normalized resonances, head only (zero elsewhere)
__device__ float d_ssp[RE*256];    // sum-of-squares partials
__device__ float d_Pr[ORE], d_Pi[ORE];   // modal prefactors for g (scaled by ninv)
__device__ float d_g[RE*NS];       // g = (imp (*) res_normalized)
__device__ float d_rc[NCPD*NS];    // routed_c
__device__ float d_xv[NRES*NS];    // per-res tanh terms

// ------------------- K1: params, softmaxes, impulse, routing -----------------
__global__ void k_setup(const float* __restrict__ ctrl,  const float* __restrict__ defo,
                        const float* __restrict__ noise, const float* __restrict__ attack,
                        const float* __restrict__ router,const float* __restrict__ mixp,
                        const float* __restrict__ gains, const float* __restrict__ damping,
                        const float* __restrict__ mass,  const float* __restrict__ tension,
                        const float* __restrict__ idisp, const float* __restrict__ amps,
                        float* __restrict__ out, int out_size)
{
    int b = blockIdx.x, tid = threadIdx.x;
    if (b == 0) {
        __shared__ int snc[ORE];
        int idx = tid;
        float m   = 1.0f / (1.0f + expf(-mass[idx]));
        float dmp = (1.0f / (1.0f + expf(-damping[idx]))) * 30.0f;
        float ten = exp10f(tension[idx]);
        float x0  = idisp[idx];
        float xd  = dmp / (2.0f * m);
        float om2 = fmaxf(__fsub_rn(ten, __fmul_rn(xd, xd)), 1e-12f);
        float om  = sqrtf(om2);
        float phi = atan2f(__fmul_rn(xd, x0), __fmul_rn(x0, om));
        float a   = x0 / cosf(phi);
        float amp = amps[idx];
        float amp2 = __fmul_rn(amp, amp);
        d_xd[idx] = xd; d_om[idx] = om; d_phi[idx] = phi; d_aa[idx] = a; d_am[idx] = amp2;
        double bd = (double)om * (10.0 / 65535.0);
        d_sc[idx] = (float)cos(bd);
        d_sn[idx] = (float)sin(bd);
        d_ed[idx] = expf(-xd * DELTA);
        float coef = fabsf(a) * amp2;
        float tcut = (logf(coef + 1e-30f) + 34.0f) / xd;
        int nc = (tcut <= 0.0f) ? 0 : (int)(tcut / DELTA) + 2;
        nc = min(nc, NS);
        d_nco[idx] = nc;
        snc[idx] = nc;
        __syncthreads();
        if (tid < RE) {
            int mx = 0;
            #pragma unroll
            for (int o = 0; o < NOSC; ++o) mx = max(mx, snc[o*RE + tid]);
            d_Lg[tid] = min(mx + WIN, NS);
        }
    } else if (b == 1) {
        if (tid < DEFF) {
            float v0 = 1.0f + defo[tid];
            float v1 = defo[DEFF + tid];
            float mx = fmaxf(v0, v1);
            float e0 = expf(v0 - mx), e1 = expf(v1 - mx);
            float inv = 1.0f / (e0 + e1);
            d_dsm[tid]        = e0 * inv;
            d_dsm[DEFF + tid] = e1 * inv;
        } else if (tid < DEFF + NRES) {
            int r = tid - DEFF;
            float a0 = mixp[r*2], a1 = mixp[r*2+1];
            float mx = fmaxf(a0, a1);
            float e0 = expf(a0 - mx), e1 = expf(a1 - mx);
            float inv = 1.0f / (e0 + e1);
            d_m0[r] = e0 * inv; d_m1[r] = e1 * inv;
            d_ga[r] = fabsf(gains[r]);
        }
    } else if (b < 66) {
        int i = (b - 2) * 512 + tid;                 // 0..32767
        d_imp[i] = attack[i] * noise[i];
    } else {
        int i = (b - 66) * 512 + tid;                // 0..8191
        int r = i >> 9, f = i & 511;
        float acc = 0.0f;
        #pragma unroll
        for (int c = 0; c < NCPD; ++c)
            acc = fmaf(ctrl[c*FRAMES + f], router[c*NRES + r], acc);
        d_routed[i] = acc;
        if (OB + i < out_size) out[OB + i] = acc;    // before_upsample output
    }
}

// -------------- K2: materialize resonances + sum-of-squares partials ---------
__global__ void __launch_bounds__(256) k_res()
{
    int re  = blockIdx.y;
    int tid = threadIdx.x;
    int n   = blockIdx.x * 256 + tid;

    __shared__ float sxd[NOSC], som[NOSC], sphi[NOSC], sa[NOSC], sam[NOSC];
    __shared__ int   snc[NOSC], sncm;
    if (tid < NOSC) {
        int idx = tid * RE + re;
        sxd[tid] = d_xd[idx]; som[tid] = d_om[idx]; sphi[tid] = d_phi[idx];
        sa[tid]  = d_aa[idx]; sam[tid] = d_am[idx]; snc[tid]  = d_nco[idx];
    }
    __syncthreads();
    if (tid == 0) {
        int mx = 0;
        #pragma unroll
        for (int o = 0; o < NOSC; ++o) mx = max(mx, snc[o]);
        sncm = mx;
    }
    __syncthreads();
    if (blockIdx.x * 256 >= sncm) {      // acc would be exactly 0 for whole block
        if (tid == 0) d_ssp[re*256 + blockIdx.x] = 0.0f;
        return;
    }

    float t = __fmul_rn((float)n, DELTA);
    float acc = 0.0f;
    #pragma unroll
    for (int o = 0; o < NOSC; ++o) {
        if (n < snc[o]) {
            float env = expf(-__fmul_rn(sxd[o], t));
            float arg = __fsub_rn(__fmul_rn(som[o], t), sphi[o]);  // match ref rounding
            float z   = __fmul_rn(__fmul_rn(sa[o], env), cosf(arg));
            acc = __fadd_rn(acc, __fmul_rn(z, sam[o]));
        }
    }
    if (n < 10) acc = __fmul_rn(acc, __fmul_rn((float)n, 1.0f/9.0f));   // ramp
    if (n < RESN) d_res[re*RESN + n] = acc;          // only the FIR head is read

    __shared__ float red[256];
    red[tid] = acc * acc;
    __syncthreads();
    for (int s = 128; s > 0; s >>= 1) {
        if (tid < s) red[tid] += red[tid + s];
        __syncthreads();
    }
    if (tid == 0) d_ssp[re*256 + blockIdx.x] = red[0];
}

// ------- K3: modal prefactors (norm reduction inlined; k_norm deleted) -------
__global__ void __launch_bounds__(256) k_pref()
{
    int w   = blockIdx.x;            // mode 0..511
    int tid = threadIdx.x;
    int re  = w & 31;
    int r   = re >> 1;

    // inline norm: reduce 256 SS partials -> ninv (same tree as old k_norm)
    __shared__ float nred[256];
    __shared__ float sninv;
    nred[tid] = d_ssp[re*256 + tid];
    __syncthreads();
    for (int s = 128; s > 0; s >>= 1) {
        if (tid < s) nred[tid] += nred[tid + s];
        __syncthreads();
    }
    if (tid == 0) sninv = 1.0f / (sqrtf(nred[0]) + 1e-8f);

    __shared__ float sb12, sbrest, sstepc, ssteps;
    if (tid == 0) {
        double beta_d = (double)d_om[w] * (10.0 / 65535.0);
        float b12 = __int_as_float(__float_as_int((float)beta_d) & 0xFFFFF000u);
        sb12   = b12;
        sbrest = (float)(beta_d - (double)b12);
        sstepc = (float)cos(beta_d);
        ssteps = (float)sin(beta_d);
    }
    __syncthreads();

    float xd = d_xd[w];
    float b12 = sb12, brest = sbrest, stepc = sstepc, steps = ssteps;

    const double TPd = 6.283185307179586476925287;
    const float  TPH = 6.28125f;
    const float  TPM = (float)(TPd - (double)TPH);
    const float  TPL = (float)(TPd - (double)TPH - (double)(float)(TPd - (double)TPH));
    const float  INV2PI = 0.15915494309189535f;

    int   k0 = tid * 8;
    float kf = (float)k0;
    float phi0 = kf * b12;                        // exact (8+12 mantissa bits)
    float q  = rintf(phi0 * INV2PI);
    float rp = fmaf(-q, TPH, phi0);               // q*TPH exact
    rp = fmaf(-q, TPM, rp);
    rp = fmaf(-q, TPL, rp);
    rp = fmaf(kf, brest, rp);
    float c, s;
    sincosf(rp, &s, &c);
    float env = expf(-xd * (kf * DELTA));
    float ef  = expf(-xd * DELTA);

    const float* impr = d_imp + r*WIN + (2047 - k0);
    float fr = 0.f, fi = 0.f;
    #pragma unroll
    for (int j = 0; j < 8; ++j) {
        float wgt = impr[-j] * env;
        fr = fmaf(wgt, c, fr);
        fi = fmaf(wgt, s, fi);
        float c2 = c*stepc - s*steps;             // rotate by beta
        float s2 = c*steps + s*stepc;
        c = c2; s = s2;
        env *= ef;
    }

    double sr = (double)fr, si = (double)fi;
    #pragma unroll
    for (int off = 16; off; off >>= 1) {
        sr += __shfl_down_sync(0xffffffffu, sr, off);
        si += __shfl_down_sync(0xffffffffu, si, off);
    }
    __shared__ double redr[8], redi[8];
    int wi = tid >> 5, lane = tid & 31;
    if (lane == 0) { redr[wi] = sr; redi[wi] = si; }
    __syncthreads();
    if (tid == 0) {
        double Sr = 0.0, Si = 0.0;
        #pragma unroll
        for (int i = 0; i < 8; ++i) { Sr += redr[i]; Si += redi[i]; }
        float phi = d_phi[w];
        float a   = d_aa[w], am = d_am[w];
        float cp = cosf(phi), sp = sinf(phi);
        float Ar =  a * am * cp;
        float Ai = -a * am * sp;          // A = a*amp^2 * e^{-i phi}
        float Cr = (float)Sr, Ci = (float)Si;
        d_Pr[w] = (Ar*Cr - Ai*Ci) * sninv;
        d_Pi[w] = (Ar*Ci + Ai*Cr) * sninv;
    }
}

// ---- K4: g materialization. bx<3: sliding-window FIR head (norm inlined);
//          bx>=3: modal tail, 32 samples/thread phasor rotation. --------------
__global__ void __launch_bounds__(256) k_g()
{
    int re  = blockIdx.y;
    int tid = threadIdx.x;

    if (blockIdx.x < HEAD/1024) {
        // ------------------------- FIR head -------------------------
        int r  = re >> 1;
        int T0 = blockIdx.x * 1024;
        int Lg = d_Lg[re];
        float* gout = d_g + re*NS + T0;

        if (T0 >= Lg) {
            #pragma unroll
            for (int k = 0; k < 4; ++k) gout[tid + k*256] = 0.0f;
            return;
        }

        // inline norm
        __shared__ float nred[256];
        __shared__ float sninv;
        nred[tid] = d_ssp[re*256 + tid];
        __syncthreads();
        for (int s = 128; s > 0; s >>= 1) {
            if (tid < s) nred[tid] += nred[tid + s];
            __syncthreads();
        }
        if (tid == 0) sninv = 1.0f / (sqrtf(nred[0]) + 1e-8f);
        __syncthreads();
        float ninv = sninv;

        __shared__ float imp_s[WIN];
        __shared__ float res_s[3076];          // [0]=pad(0), data at [1..3072]
        for (int i = tid; i < WIN; i += 256) imp_s[i] = d_imp[r*WIN + i];
        if (tid == 0) res_s[0] = 0.0f;
        for (int i = tid; i < 3072; i += 256) {
            int gi = T0 - 2047 + i;
            res_s[1 + i] = (gi >= 0) ? d_res[re*RESN + gi] : 0.0f;
        }
        __syncthreads();

        int t0l  = tid * 4;
        int base = 2048 + t0l;                 // B=1 bias included
        float w0 = res_s[base], w1 = res_s[base+1], w2 = res_s[base+2], w3 = res_s[base+3];
        float a0 = 0.f, a1 = 0.f, a2 = 0.f, a3 = 0.f;
        #pragma unroll 4
        for (int j = 0; j < WIN; j += 4) {
            float i0 = imp_s[j];
            a0 = fmaf(i0, w0, a0); a1 = fmaf(i0, w1, a1);
            a2 = fmaf(i0, w2, a2); a3 = fmaf(i0, w3, a3);
            float v1 = res_s[base - j - 1];
            float i1 = imp_s[j+1];
            a0 = fmaf(i1, v1, a0); a1 = fmaf(i1, w0, a1);
            a2 = fmaf(i1, w1, a2); a3 = fmaf(i1, w2, a3);
            float v2 = res_s[base - j - 2];
            float i2 = imp_s[j+2];
            a0 = fmaf(i2, v2, a0); a1 = fmaf(i2, v1, a1);
            a2 = fmaf(i2, w0, a2); a3 = fmaf(i2, w1, a3);
            float v3 = res_s[base - j - 3];
            float i3 = imp_s[j+3];
            a0 = fmaf(i3, v3, a0); a1 = fmaf(i3, v2, a1);
            a2 = fmaf(i3, v1, a2); a3 = fmaf(i3, w0, a3);
            w0 = res_s[base - j - 4]; w1 = v3; w2 = v2; w3 = v1;
        }
        gout[t0l    ] = a0 * ninv;
        gout[t0l + 1] = a1 * ninv;
        gout[t0l + 2] = a2 * ninv;
        gout[t0l + 3] = a3 * ninv;
        return;
    }

    // ------------------------- modal tail -------------------------
    int T0 = HEAD + (blockIdx.x - HEAD/1024) * 8192;
    int n0 = T0 + tid * 32;

    __shared__ float sxd[NOSC], som[NOSC], spr[NOSC], spi[NOSC];
    __shared__ float ssc[NOSC], ssn[NOSC], sed[NOSC];
    __shared__ int   sgc[NOSC];
    if (tid < NOSC) {
        int idx = tid * RE + re;
        sxd[tid] = d_xd[idx]; som[tid] = d_om[idx];
        spr[tid] = d_Pr[idx]; spi[tid] = d_Pi[idx];
        ssc[tid] = d_sc[idx]; ssn[tid] = d_sn[idx]; sed[tid] = d_ed[idx];
        sgc[tid] = d_nco[idx] + WIN;     // per-mode g support
    }
    __syncthreads();                     // BEFORE any early exit (R10 lesson)

    if (n0 >= NS) return;
    int Lg = d_Lg[re];
    float* gp = d_g + re*NS + n0;

    if (n0 >= Lg) {                      // g numerically zero here
        #pragma unroll
        for (int j = 0; j < 32; j += 4)
            *reinterpret_cast<float4*>(gp + j) = make_float4(0.f, 0.f, 0.f, 0.f);
        return;
    }

    float acc[32];
    #pragma unroll
    for (int j = 0; j < 32; ++j) acc[j] = 0.f;

    float tau0 = __fmul_rn((float)(n0 - 2047), DELTA);
    #pragma unroll
    for (int o = 0; o < NOSC; ++o) {
        if (n0 < sgc[o]) {
            float s, c;
            sincosf(som[o] * tau0, &s, &c);
            float env = expf(-sxd[o] * tau0);
            float pr = spr[o], pi = spi[o];
            float sc = ssc[o], sn = ssn[o], ed = sed[o];
            #pragma unroll
            for (int j = 0; j < 32; ++j) {
                acc[j] = fmaf(env, pr*c - pi*s, acc[j]);
                float c2 = c*sc - s*sn;
                float s2 = c*sn + s*sc;
                c = c2; s = s2;
                env *= ed;
            }
        }
    }
    #pragma unroll
    for (int j = 0; j < 32; j += 4)
        *reinterpret_cast<float4*>(gp + j) = make_float4(acc[j], acc[j+1], acc[j+2], acc[j+3]);
}

// ---- K5: conv (gather taps on g) + inline rc + deform mix + res mix + tanh --
__global__ void __launch_bounds__(256) k_conv()
{
    int r  = blockIdx.y;
    int N0 = blockIdx.x * 512;
    int tid = threadIdx.x;

    __shared__ float rt_s[FRAMES];
    __shared__ float imp_r[WIN];
    for (int i = tid; i < FRAMES; i += 256) rt_s[i] = d_routed[r*FRAMES + i];
    for (int i = tid; i < WIN; i += 256)    imp_r[i] = d_imp[r*WIN + i];
    __syncthreads();

    const float* g0 = d_g + (2*r)*NS;
    const float* g1 = g0 + NS;
    int LgM = max(d_Lg[2*r], d_Lg[2*r + 1]);
    float m0v = d_m0[r], m1v = d_m1[r], gav = d_ga[r];

    #pragma unroll
    for (int h = 0; h < 2; ++h) {
        int n = N0 + tid + h*256;
        float cpos = __fsub_rn(__fmul_rn((float)n + 0.5f, 1.0f/256.0f), 0.5f);
        float fl = floorf(cpos);
        int   i0 = (int)fl;
        float w  = cpos - fl;
        int k0 = max(i0, 0);
        int k1 = min(i0 + 1, DEFF - 1);
        float w0 = 1.0f - w;
        float dv0 = __fadd_rn(__fmul_rn(w0, d_dsm[k0]),        __fmul_rn(w, d_dsm[k1]));
        float dv1 = __fadd_rn(__fmul_rn(w0, d_dsm[DEFF + k0]), __fmul_rn(w, d_dsm[DEFF + k1]));

        int fhi = n >> 7;
        // rc: 16-tap sparse conv with impulse (same order/values as old k_rc)
        int flo2 = max(0, (n - (WIN - 1) + 127) >> 7);
        float arc = 0.0f;
        for (int f = flo2; f <= fhi; ++f)
            arc = fmaf(rt_s[f], imp_r[n - (f << 7)], arc);
        // conv taps on g
        int flo = max(0, (n - LgM + 128) >> 7);
        float c0 = 0.f, c1 = 0.f;
        for (int f = flo; f <= fhi; ++f) {
            float rf = rt_s[f];
            int k = n - (f << 7);
            c0 = fmaf(rf, __ldg(g0 + k), c0);
            c1 = fmaf(rf, __ldg(g1 + k), c1);
        }
        float x  = __fadd_rn(__fmul_rn(dv0, c0), __fmul_rn(dv1, c1));
        float x2 = __fadd_rn(__fmul_rn(m0v, arc), __fmul_rn(m1v, x));
        d_xv[r*NS + n] = tanhf(__fmul_rn(x2, gav));
        d_rc[r*NS + n] = arc;
    }
}

// -------------------- K6: final reductions over res / cpd --------------------
__global__ void __launch_bounds__(256) k_out(float* __restrict__ out, int out_size)
{
    int n = blockIdx.x * 256 + threadIdx.x;
    float s = 0.0f;
    #pragma unroll
    for (int r = 0; r < NRES; ++r) s = __fadd_rn(s, d_xv[r*NS + n]);
    float cs = 0.0f;
    #pragma unroll
    for (int c = 0; c < NCPD; ++c) cs = __fadd_rn(cs, d_rc[c*NS + n]);
    out[n] = s;
    if (OC + n < out_size) out[OC + n] = cs;
}

// ------------------------------------------------------------------------------
extern "C" void kernel_launch(void* const* d_in, const int* in_sizes, int n_in,
                              void* d_out, int out_size)
{
    const float* ctrl    = (const float*)d_in[0];
    const float* defo    = (const float*)d_in[1];
    const float* noise   = (const float*)d_in[2];
    const float* attack  = (const float*)d_in[3];
    const float* router  = (const float*)d_in[4];
    const float* mixp    = (const float*)d_in[5];
    const float* gains   = (const float*)d_in[6];
    const float* damping = (const float*)d_in[7];
    const float* mass    = (const float*)d_in[8];
    const float* tension = (const float*)d_in[9];
    const float* idisp   = (const float*)d_in[10];
    const float* amps    = (const float*)d_in[11];
    float* out = (float*)d_out;

    k_setup<<<82, 512>>>(ctrl, defo, noise, attack, router, mixp, gains,
                         damping, mass, tension, idisp, amps, out, out_size);
    k_res  <<<dim3(256, RE),   256>>>();
    k_pref <<<ORE,             256>>>();
    k_g    <<<dim3(11, RE),    256>>>();   // 4th launch -> ncu capture slot
    k_conv <<<dim3(128, NRES), 256>>>();
    k_out  <<<256,             256>>>(out, out_size);
}

// round 13
// speedup vs baseline: 1.3233x; 1.3233x over previous
#include <cuda_runtime.h>
#include <cuda_bf16.h>

#define NS      65536
#define NRES    16
#define NOSC    16
#define NCPD    16
#define WIN     2048
#define FRAMES  512
#define DEFF    256
#define RE      32            // NRES*NEXPR
#define ORE     512           // NOSC*NRES*NEXPR
#define OB      65536         // out offset: before_upsample
#define OC      73728         // out offset: cs
#define DELTA   (10.0f/65535.0f)
#define HEAD    3072          // direct-FIR head length (>= 2057, mult of 1024)

// ----------------------------- device scratch --------------------------------
__device__ float d_xd[ORE], d_om[ORE], d_phi[ORE], d_aa[ORE], d_am[ORE];
__device__ float d_sc[ORE], d_sn[ORE], d_ed[ORE];   // per-mode step cos/sin, env step
__device__ int   d_nco[ORE];
__device__ int   d_Lg[RE], d_ncm[RE];
__device__ float d_routed[NRES*FRAMES];
__device__ float d_imp[NCPD*WIN];
__device__ float d_dsm[2*DEFF];
__device__ float d_m0[NRES], d_m1[NRES], d_ga[NRES];
__device__ float d_res[RE*NS];     // un-normalized resonances (zero past cutoff)
__device__ float d_ssp[RE*256];    // sum-of-squares partials
__device__ float d_ninv[RE];       // 1/(||res||+1e-8)
__device__ float d_Pr[ORE], d_Pi[ORE];   // modal prefactors for g (scaled by ninv)
__device__ float d_g[RE*NS];       // g = (imp (*) res_normalized)
__device__ float d_rc[NCPD*NS];    // routed_c
__device__ float d_xv[NRES*NS];    // per-res tanh terms

// ------------------- K1: params, softmaxes, impulse, routing -----------------
__global__ void k_setup(const float* __restrict__ ctrl,  const float* __restrict__ defo,
                        const float* __restrict__ noise, const float* __restrict__ attack,
                        const float* __restrict__ router,const float* __restrict__ mixp,
                        const float* __restrict__ gains, const float* __restrict__ damping,
                        const float* __restrict__ mass,  const float* __restrict__ tension,
                        const float* __restrict__ idisp, const float* __restrict__ amps,
                        float* __restrict__ out, int out_size)
{
    int b = blockIdx.x, tid = threadIdx.x;
    if (b == 0) {
        __shared__ int snc[ORE];
        int idx = tid;
        float m   = 1.0f / (1.0f + expf(-mass[idx]));
        float dmp = (1.0f / (1.0f + expf(-damping[idx]))) * 30.0f;
        float ten = exp10f(tension[idx]);
        float x0  = idisp[idx];
        float xd  = dmp / (2.0f * m);
        float om2 = fmaxf(__fsub_rn(ten, __fmul_rn(xd, xd)), 1e-12f);
        float om  = sqrtf(om2);
        float phi = atan2f(__fmul_rn(xd, x0), __fmul_rn(x0, om));
        float a   = x0 / cosf(phi);
        float amp = amps[idx];
        float amp2 = __fmul_rn(amp, amp);
        d_xd[idx] = xd; d_om[idx] = om; d_phi[idx] = phi; d_aa[idx] = a; d_am[idx] = amp2;
        double bd = (double)om * (10.0 / 65535.0);
        d_sc[idx] = (float)cos(bd);
        d_sn[idx] = (float)sin(bd);
        d_ed[idx] = expf(-xd * DELTA);
        float coef = fabsf(a) * amp2;
        float tcut = (logf(coef + 1e-30f) + 34.0f) / xd;
        int nc = (tcut <= 0.0f) ? 0 : (int)(tcut / DELTA) + 2;
        nc = min(nc, NS);
        d_nco[idx] = nc;
        snc[idx] = nc;
        __syncthreads();
        if (tid < RE) {
            int mx = 0;
            #pragma unroll
            for (int o = 0; o < NOSC; ++o) mx = max(mx, snc[o*RE + tid]);
            d_ncm[tid] = mx;
            d_Lg[tid]  = min(mx + WIN, NS);
        }
    } else if (b == 1) {
        if (tid < DEFF) {
            float v0 = 1.0f + defo[tid];
            float v1 = defo[DEFF + tid];
            float mx = fmaxf(v0, v1);
            float e0 = expf(v0 - mx), e1 = expf(v1 - mx);
            float inv = 1.0f / (e0 + e1);
            d_dsm[tid]        = e0 * inv;
            d_dsm[DEFF + tid] = e1 * inv;
        } else if (tid < DEFF + NRES) {
            int r = tid - DEFF;
            float a0 = mixp[r*2], a1 = mixp[r*2+1];
            float mx = fmaxf(a0, a1);
            float e0 = expf(a0 - mx), e1 = expf(a1 - mx);
            float inv = 1.0f / (e0 + e1);
            d_m0[r] = e0 * inv; d_m1[r] = e1 * inv;
            d_ga[r] = fabsf(gains[r]);
        }
    } else if (b < 66) {
        int i = (b - 2) * 512 + tid;                 // 0..32767
        d_imp[i] = attack[i] * noise[i];
    } else {
        int i = (b - 66) * 512 + tid;                // 0..8191
        int r = i >> 9, f = i & 511;
        float acc = 0.0f;
        #pragma unroll
        for (int c = 0; c < NCPD; ++c)
            acc = fmaf(ctrl[c*FRAMES + f], router[c*NRES + r], acc);
        d_routed[i] = acc;
        if (OB + i < out_size) out[OB + i] = acc;    // before_upsample output
    }
}

// -------------- K2: materialize resonances + sum-of-squares partials ---------
__global__ void __launch_bounds__(256) k_res()
{
    int re  = blockIdx.y;
    int tid = threadIdx.x;
    int n   = blockIdx.x * 256 + tid;

    __shared__ float sxd[NOSC], som[NOSC], sphi[NOSC], sa[NOSC], sam[NOSC];
    __shared__ int   snc[NOSC];
    if (tid < NOSC) {
        int idx = tid * RE + re;
        sxd[tid] = d_xd[idx]; som[tid] = d_om[idx]; sphi[tid] = d_phi[idx];
        sa[tid]  = d_aa[idx]; sam[tid] = d_am[idx]; snc[tid]  = d_nco[idx];
    }
    __syncthreads();

    float t = __fmul_rn((float)n, DELTA);
    float acc = 0.0f;
    #pragma unroll
    for (int o = 0; o < NOSC; ++o) {
        if (n < snc[o]) {
            float env = expf(-__fmul_rn(sxd[o], t));
            float arg = __fsub_rn(__fmul_rn(som[o], t), sphi[o]);  // match ref rounding
            float z   = __fmul_rn(__fmul_rn(sa[o], env), cosf(arg));
            acc = __fadd_rn(acc, __fmul_rn(z, sam[o]));
        }
    }
    if (n < 10) acc = __fmul_rn(acc, __fmul_rn((float)n, 1.0f/9.0f));   // ramp
    d_res[re*NS + n] = acc;

    __shared__ float red[256];
    red[tid] = acc * acc;
    __syncthreads();
    for (int s = 128; s > 0; s >>= 1) {
        if (tid < s) red[tid] += red[tid + s];
        __syncthreads();
    }
    if (tid == 0) d_ssp[re*256 + blockIdx.x] = red[0];
}

// ----------------------------- K3: 1/(norm+1e-8) -----------------------------
__global__ void k_norm()
{
    int re = blockIdx.x, tid = threadIdx.x;
    __shared__ float red[256];
    red[tid] = d_ssp[re*256 + tid];
    __syncthreads();
    for (int s = 128; s > 0; s >>= 1) {
        if (tid < s) red[tid] += red[tid + s];
        __syncthreads();
    }
    if (tid == 0) d_ninv[re] = 1.0f / (sqrtf(red[0]) + 1e-8f);
}

// -------------- K4: direct FIR head of g (n < HEAD only) ---------------------
// Thread->output remap vs R11: thread owns outputs {tid, tid+256, tid+512,
// tid+768} so res_s lane addressing is stride-1 (conflict-free) instead of
// stride-4 (4-way bank conflict). Same j-ascending order => bit-identical g.
__global__ void __launch_bounds__(256) k_gfir()
{
    int re = blockIdx.y;
    int r  = re >> 1;
    int T0 = blockIdx.x * 1024;
    int Lg = d_Lg[re];
    float* gout = d_g + re*NS + T0;
    int tid = threadIdx.x;

    if (T0 >= Lg) {
        #pragma unroll
        for (int k = 0; k < 4; ++k) gout[tid + k*256] = 0.0f;
        return;
    }

    __shared__ float imp_s[WIN];
    __shared__ float res_s[3072];
    for (int i = tid; i < WIN; i += 256) imp_s[i] = d_imp[r*WIN + i];
    for (int i = tid; i < 3072; i += 256) {
        int gi = T0 - 2047 + i;
        res_s[i] = (gi >= 0) ? d_res[re*NS + gi] : 0.0f;
    }
    __syncthreads();

    float ninv = d_ninv[re];
    float a0 = 0.f, a1 = 0.f, a2 = 0.f, a3 = 0.f;
    #pragma unroll 8
    for (int j = 0; j < WIN; ++j) {
        float ij = imp_s[j];
        int bi = 2047 + tid - j;        // stride-1 across lanes
        a0 = fmaf(ij, res_s[bi      ], a0);
        a1 = fmaf(ij, res_s[bi + 256], a1);
        a2 = fmaf(ij, res_s[bi + 512], a2);
        a3 = fmaf(ij, res_s[bi + 768], a3);
    }
    gout[tid      ] = a0 * ninv;
    gout[tid + 256] = a1 * ninv;
    gout[tid + 512] = a2 * ninv;
    gout[tid + 768] = a3 * ninv;
}

// ------- K5: modal prefactors  P_o = ninv * A_o * sum_j imp[j] e^{s(2047-j)D}
__global__ void __launch_bounds__(256) k_pref()
{
    int w   = blockIdx.x;            // mode 0..511
    int tid = threadIdx.x;
    int re  = w & 31;
    int r   = re >> 1;

    __shared__ float sb12, sbrest, sstepc, ssteps;
    if (tid == 0) {
        double beta_d = (double)d_om[w] * (10.0 / 65535.0);
        float b12 = __int_as_float(__float_as_int((float)beta_d) & 0xFFFFF000u);
        sb12   = b12;
        sbrest = (float)(beta_d - (double)b12);
        sstepc = (float)cos(beta_d);
        ssteps = (float)sin(beta_d);
    }
    __syncthreads();

    float xd = d_xd[w];
    float b12 = sb12, brest = sbrest, stepc = sstepc, steps = ssteps;

    const double TPd = 6.283185307179586476925287;
    const float  TPH = 6.28125f;
    const float  TPM = (float)(TPd - (double)TPH);
    const float  TPL = (float)(TPd - (double)TPH - (double)(float)(TPd - (double)TPH));
    const float  INV2PI = 0.15915494309189535f;

    int   k0 = tid * 8;
    float kf = (float)k0;
    float phi0 = kf * b12;                        // exact (8+12 mantissa bits)
    float q  = rintf(phi0 * INV2PI);
    float rp = fmaf(-q, TPH, phi0);               // q*TPH exact
    rp = fmaf(-q, TPM, rp);
    rp = fmaf(-q, TPL, rp);
    rp = fmaf(kf, brest, rp);
    float c, s;
    sincosf(rp, &s, &c);
    float env = expf(-xd * (kf * DELTA));
    float ef  = expf(-xd * DELTA);

    const float* impr = d_imp + r*WIN + (2047 - k0);
    float fr = 0.f, fi = 0.f;
    #pragma unroll
    for (int j = 0; j < 8; ++j) {
        float wgt = impr[-j] * env;
        fr = fmaf(wgt, c, fr);
        fi = fmaf(wgt, s, fi);
        float c2 = c*stepc - s*steps;             // rotate by beta
        float s2 = c*steps + s*stepc;
        c = c2; s = s2;
        env *= ef;
    }

    double sr = (double)fr, si = (double)fi;
    #pragma unroll
    for (int off = 16; off; off >>= 1) {
        sr += __shfl_down_sync(0xffffffffu, sr, off);
        si += __shfl_down_sync(0xffffffffu, si, off);
    }
    __shared__ double redr[8], redi[8];
    int wi = tid >> 5, lane = tid & 31;
    if (lane == 0) { redr[wi] = sr; redi[wi] = si; }
    __syncthreads();
    if (tid == 0) {
        double Sr = 0.0, Si = 0.0;
        #pragma unroll
        for (int i = 0; i < 8; ++i) { Sr += redr[i]; Si += redi[i]; }
        float phi = d_phi[w];
        float a   = d_aa[w], am = d_am[w];
        float cp = cosf(phi), sp = sinf(phi);
        float Ar =  a * am * cp;
        float Ai = -a * am * sp;          // A = a*amp^2 * e^{-i phi}
        float ninv = d_ninv[re];
        float Cr = (float)Sr, Ci = (float)Si;
        d_Pr[w] = (Ar*Cr - Ai*Ci) * ninv;
        d_Pi[w] = (Ar*Ci + Ai*Cr) * ninv;
    }
}

// -------------- K6: modal tail of g — 32 samples/thread, phasor rotation ----
// smem load + barrier happen BEFORE any early exit (R10 lesson).
__global__ void __launch_bounds__(256) k_gmod()
{
    int re  = blockIdx.y;
    int tid = threadIdx.x;
    int T0  = HEAD + blockIdx.x * 8192;
    int n0  = T0 + tid * 32;

    __shared__ float sxd[NOSC], som[NOSC], spr[NOSC], spi[NOSC];
    __shared__ float ssc[NOSC], ssn[NOSC], sed[NOSC];
    __shared__ int   sgc[NOSC];
    if (tid < NOSC) {
        int idx = tid * RE + re;
        sxd[tid] = d_xd[idx]; som[tid] = d_om[idx];
        spr[tid] = d_Pr[idx]; spi[tid] = d_Pi[idx];
        ssc[tid] = d_sc[idx]; ssn[tid] = d_sn[idx]; sed[tid] = d_ed[idx];
        sgc[tid] = d_nco[idx] + WIN;     // per-mode g support
    }
    __syncthreads();

    if (n0 >= NS) return;
    int Lg  = d_Lg[re];
    float* gp = d_g + re*NS + n0;

    if (n0 >= Lg) {                      // g numerically zero here
        #pragma unroll
        for (int j = 0; j < 32; j += 4)
            *reinterpret_cast<float4*>(gp + j) = make_float4(0.f, 0.f, 0.f, 0.f);
        return;
    }

    float acc[32];
    #pragma unroll
    for (int j = 0; j < 32; ++j) acc[j] = 0.f;

    float tau0 = __fmul_rn((float)(n0 - 2047), DELTA);
    #pragma unroll
    for (int o = 0; o < NOSC; ++o) {
        if (n0 < sgc[o]) {               // skip fully-negligible modes
            float s, c;
            sincosf(som[o] * tau0, &s, &c);
            float env = expf(-sxd[o] * tau0);
            float pr = spr[o], pi = spi[o];
            float sc = ssc[o], sn = ssn[o], ed = sed[o];
            #pragma unroll
            for (int j = 0; j < 32; ++j) {
                acc[j] = fmaf(env, pr*c - pi*s, acc[j]);
                float c2 = c*sc - s*sn;  // rotate phase by beta
                float s2 = c*sn + s*sc;
                c = c2; s = s2;
                env *= ed;               // advance envelope
            }
        }
    }
    #pragma unroll
    for (int j = 0; j < 32; j += 4)
        *reinterpret_cast<float4*>(gp + j) = make_float4(acc[j], acc[j+1], acc[j+2], acc[j+3]);
}

// ------------------ K7: routed_c (16-tap sparse convolution) -----------------
__global__ void __launch_bounds__(256) k_rc()
{
    int c = blockIdx.y;
    int n = blockIdx.x * 256 + threadIdx.x;
    int fhi = n >> 7;
    int flo = max(0, (n - (WIN - 1) + 127) >> 7);
    const float* rt = d_routed + c*FRAMES;
    const float* im = d_imp    + c*WIN;
    float acc = 0.0f;
    for (int f = flo; f <= fhi; ++f)
        acc = fmaf(rt[f], im[n - (f << 7)], acc);
    d_rc[c*NS + n] = acc;
}

// -------- K8: conv-apply (sparse taps on g), deform mix, res mix, tanh -------
__global__ void __launch_bounds__(256) k_conv()
{
    int r  = blockIdx.y;
    int N0 = blockIdx.x * 512;
    int tid = threadIdx.x;

    __shared__ float rt_s[FRAMES];
    for (int i = tid; i < FRAMES; i += 256) rt_s[i] = d_routed[r*FRAMES + i];
    __syncthreads();

    const float* g0 = d_g + (2*r)*NS;
    const float* g1 = g0 + NS;
    int LgM = max(d_Lg[2*r], d_Lg[2*r + 1]);
    float m0v = d_m0[r], m1v = d_m1[r], gav = d_ga[r];

    #pragma unroll
    for (int h = 0; h < 2; ++h) {
        int n = N0 + tid + h*256;
        float cpos = __fsub_rn(__fmul_rn((float)n + 0.5f, 1.0f/256.0f), 0.5f);
        float fl = floorf(cpos);
        int   i0 = (int)fl;
        float w  = cpos - fl;
        int k0 = max(i0, 0);
        int k1 = min(i0 + 1, DEFF - 1);
        float w0 = 1.0f - w;
        float dv0 = __fadd_rn(__fmul_rn(w0, d_dsm[k0]),        __fmul_rn(w, d_dsm[k1]));
        float dv1 = __fadd_rn(__fmul_rn(w0, d_dsm[DEFF + k0]), __fmul_rn(w, d_dsm[DEFF + k1]));

        int fhi = n >> 7;
        int flo = max(0, (n - LgM + 128) >> 7);
        float c0 = 0.f, c1 = 0.f;
        for (int f = flo; f <= fhi; ++f) {
            float rf = rt_s[f];
            int k = n - (f << 7);
            c0 = fmaf(rf, __ldg(g0 + k), c0);
            c1 = fmaf(rf, __ldg(g1 + k), c1);
        }
        float x  = __fadd_rn(__fmul_rn(dv0, c0), __fmul_rn(dv1, c1));
        float rc = d_rc[r*NS + n];
        float x2 = __fadd_rn(__fmul_rn(m0v, rc), __fmul_rn(m1v, x));
        d_xv[r*NS + n] = tanhf(__fmul_rn(x2, gav));
    }
}

// -------------------- K9: final reductions over res / cpd --------------------
__global__ void __launch_bounds__(256) k_out(float* __restrict__ out, int out_size)
{
    int n = blockIdx.x * 256 + threadIdx.x;
    float s = 0.0f;
    #pragma unroll
    for (int r = 0; r < NRES; ++r) s = __fadd_rn(s, d_xv[r*NS + n]);
    float cs = 0.0f;
    #pragma unroll
    for (int c = 0; c < NCPD; ++c) cs = __fadd_rn(cs, d_rc[c*NS + n]);
    out[n] = s;
    if (OC + n < out_size) out[OC + n] = cs;
}

// ------------------------------------------------------------------------------
extern "C" void kernel_launch(void* const* d_in, const int* in_sizes, int n_in,
                              void* d_out, int out_size)
{
    const float* ctrl    = (const float*)d_in[0];
    const float* defo    = (const float*)d_in[1];
    const float* noise   = (const float*)d_in[2];
    const float* attack  = (const float*)d_in[3];
    const float* router  = (const float*)d_in[4];
    const float* mixp    = (const float*)d_in[5];
    const float* gains   = (const float*)d_in[6];
    const float* damping = (const float*)d_in[7];
    const float* mass    = (const float*)d_in[8];
    const float* tension = (const float*)d_in[9];
    const float* idisp   = (const float*)d_in[10];
    const float* amps    = (const float*)d_in[11];
    float* out = (float*)d_out;

    k_setup<<<82, 512>>>(ctrl, defo, noise, attack, router, mixp, gains,
                         damping, mass, tension, idisp, amps, out, out_size);
    k_res  <<<dim3(256, RE),   256>>>();
    k_norm <<<RE,              256>>>();
    k_gfir <<<dim3(HEAD/1024, RE), 256>>>();   // 4th launch -> ncu capture slot
    k_pref <<<ORE,             256>>>();       // needs only norm/setup; after gfir OK
    k_gmod <<<dim3(8, RE),     256>>>();
    k_rc   <<<dim3(256, NCPD), 256>>>();
    k_conv <<<dim3(128, NRES), 256>>>();
    k_out  <<<256,             256>>>(out, out_size);
}

// round 14
// speedup vs baseline: 1.5094x; 1.1406x over previous
#include <cuda_runtime.h>
#include <cuda_bf16.h>

#define NS      65536
#define NRES    16
#define NOSC    16
#define NCPD    16
#define WIN     2048
#define FRAMES  512
#define DEFF    256
#define RE      32            // NRES*NEXPR
#define ORE     512           // NOSC*NRES*NEXPR
#define OB      65536         // out offset: before_upsample
#define OC      73728         // out offset: cs
#define DELTA   (10.0f/65535.0f)
#define HEAD    3072          // direct-FIR head length (>= 2057, mult of 1024)

// ----------------------------- device scratch --------------------------------
__device__ float d_xd[ORE], d_om[ORE], d_phi[ORE], d_aa[ORE], d_am[ORE];
__device__ float d_sc[ORE], d_sn[ORE], d_ed[ORE];   // per-mode step cos/sin, env step
__device__ int   d_nco[ORE];
__device__ int   d_Lg[RE], d_ncm[RE];
__device__ float d_routed[NRES*FRAMES];
__device__ float d_imp[NCPD*WIN];
__device__ float d_dsm[2*DEFF];
__device__ float d_m0[NRES], d_m1[NRES], d_ga[NRES];
__device__ float d_res[RE*NS];     // un-normalized resonances (zero past cutoff)
__device__ float d_ssp[RE*256];    // sum-of-squares partials
__device__ float d_ninv[RE];       // 1/(||res||+1e-8)
__device__ float d_Pr[ORE], d_Pi[ORE];   // modal prefactors for g (scaled by ninv)
__device__ float d_g[RE*NS];       // g = (imp (*) res_normalized)
__device__ float d_rc[NCPD*NS];    // routed_c
__device__ float d_xv[NRES*NS];    // per-res tanh terms

// ------------------- K1: params, softmaxes, impulse, routing -----------------
__global__ void k_setup(const float* __restrict__ ctrl,  const float* __restrict__ defo,
                        const float* __restrict__ noise, const float* __restrict__ attack,
                        const float* __restrict__ router,const float* __restrict__ mixp,
                        const float* __restrict__ gains, const float* __restrict__ damping,
                        const float* __restrict__ mass,  const float* __restrict__ tension,
                        const float* __restrict__ idisp, const float* __restrict__ amps,
                        float* __restrict__ out, int out_size)
{
    int b = blockIdx.x, tid = threadIdx.x;
    if (b == 0) {
        __shared__ int snc[ORE];
        int idx = tid;
        float m   = 1.0f / (1.0f + expf(-mass[idx]));
        float dmp = (1.0f / (1.0f + expf(-damping[idx]))) * 30.0f;
        float ten = exp10f(tension[idx]);
        float x0  = idisp[idx];
        float xd  = dmp / (2.0f * m);
        float om2 = fmaxf(__fsub_rn(ten, __fmul_rn(xd, xd)), 1e-12f);
        float om  = sqrtf(om2);
        float phi = atan2f(__fmul_rn(xd, x0), __fmul_rn(x0, om));
        float a   = x0 / cosf(phi);
        float amp = amps[idx];
        float amp2 = __fmul_rn(amp, amp);
        d_xd[idx] = xd; d_om[idx] = om; d_phi[idx] = phi; d_aa[idx] = a; d_am[idx] = amp2;
        double bd = (double)om * (10.0 / 65535.0);
        d_sc[idx] = (float)cos(bd);
        d_sn[idx] = (float)sin(bd);
        d_ed[idx] = expf(-xd * DELTA);
        float coef = fabsf(a) * amp2;
        float tcut = (logf(coef + 1e-30f) + 34.0f) / xd;
        int nc = (tcut <= 0.0f) ? 0 : (int)(tcut / DELTA) + 2;
        nc = min(nc, NS);
        d_nco[idx] = nc;
        snc[idx] = nc;
        __syncthreads();
        if (tid < RE) {
            int mx = 0;
            #pragma unroll
            for (int o = 0; o < NOSC; ++o) mx = max(mx, snc[o*RE + tid]);
            d_ncm[tid] = mx;
            d_Lg[tid]  = min(mx + WIN, NS);
        }
    } else if (b == 1) {
        if (tid < DEFF) {
            float v0 = 1.0f + defo[tid];
            float v1 = defo[DEFF + tid];
            float mx = fmaxf(v0, v1);
            float e0 = expf(v0 - mx), e1 = expf(v1 - mx);
            float inv = 1.0f / (e0 + e1);
            d_dsm[tid]        = e0 * inv;
            d_dsm[DEFF + tid] = e1 * inv;
        } else if (tid < DEFF + NRES) {
            int r = tid - DEFF;
            float a0 = mixp[r*2], a1 = mixp[r*2+1];
            float mx = fmaxf(a0, a1);
            float e0 = expf(a0 - mx), e1 = expf(a1 - mx);
            float inv = 1.0f / (e0 + e1);
            d_m0[r] = e0 * inv; d_m1[r] = e1 * inv;
            d_ga[r] = fabsf(gains[r]);
        }
    } else if (b < 66) {
        int i = (b - 2) * 512 + tid;                 // 0..32767
        d_imp[i] = attack[i] * noise[i];
    } else {
        int i = (b - 66) * 512 + tid;                // 0..8191
        int r = i >> 9, f = i & 511;
        float acc = 0.0f;
        #pragma unroll
        for (int c = 0; c < NCPD; ++c)
            acc = fmaf(ctrl[c*FRAMES + f], router[c*NRES + r], acc);
        d_routed[i] = acc;
        if (OB + i < out_size) out[OB + i] = acc;    // before_upsample output
    }
}

// -------------- K2: materialize resonances + sum-of-squares partials ---------
__global__ void __launch_bounds__(256) k_res()
{
    int re  = blockIdx.y;
    int tid = threadIdx.x;
    int n   = blockIdx.x * 256 + tid;

    __shared__ float sxd[NOSC], som[NOSC], sphi[NOSC], sa[NOSC], sam[NOSC];
    __shared__ int   snc[NOSC];
    if (tid < NOSC) {
        int idx = tid * RE + re;
        sxd[tid] = d_xd[idx]; som[tid] = d_om[idx]; sphi[tid] = d_phi[idx];
        sa[tid]  = d_aa[idx]; sam[tid] = d_am[idx]; snc[tid]  = d_nco[idx];
    }
    __syncthreads();

    float t = __fmul_rn((float)n, DELTA);
    float acc = 0.0f;
    #pragma unroll
    for (int o = 0; o < NOSC; ++o) {
        if (n < snc[o]) {
            float env = expf(-__fmul_rn(sxd[o], t));
            float arg = __fsub_rn(__fmul_rn(som[o], t), sphi[o]);  // match ref rounding
            float z   = __fmul_rn(__fmul_rn(sa[o], env), cosf(arg));
            acc = __fadd_rn(acc, __fmul_rn(z, sam[o]));
        }
    }
    if (n < 10) acc = __fmul_rn(acc, __fmul_rn((float)n, 1.0f/9.0f));   // ramp
    d_res[re*NS + n] = acc;

    __shared__ float red[256];
    red[tid] = acc * acc;
    __syncthreads();
    for (int s = 128; s > 0; s >>= 1) {
        if (tid < s) red[tid] += red[tid + s];
        __syncthreads();
    }
    if (tid == 0) d_ssp[re*256 + blockIdx.x] = red[0];
}

// ----------------------------- K3: 1/(norm+1e-8) -----------------------------
__global__ void k_norm()
{
    int re = blockIdx.x, tid = threadIdx.x;
    __shared__ float red[256];
    red[tid] = d_ssp[re*256 + tid];
    __syncthreads();
    for (int s = 128; s > 0; s >>= 1) {
        if (tid < s) red[tid] += red[tid + s];
        __syncthreads();
    }
    if (tid == 0) d_ninv[re] = 1.0f / (sqrtf(red[0]) + 1e-8f);
}

// -------------- K4: direct FIR head of g — vectorized sliding window ---------
// Thread owns 4 consecutive outputs. Per 4 taps: ONE float4 res load + ONE
// float4 imp broadcast; window rotates through registers. Per-output tap order
// stays j-ascending => bit-identical g to the scalar version.
__global__ void __launch_bounds__(256) k_gfir()
{
    int re = blockIdx.y;
    int r  = re >> 1;
    int T0 = blockIdx.x * 1024;
    int Lg = d_Lg[re];
    float* gout = d_g + re*NS + T0;
    int tid = threadIdx.x;

    if (T0 >= Lg) {
        #pragma unroll
        for (int k = 0; k < 4; ++k) gout[tid + k*256] = 0.0f;
        return;
    }

    __shared__ __align__(16) float imp_s[WIN];
    __shared__ __align__(16) float res_s[3080];    // [0]=pad(0); data at [1..3072]
    for (int i = tid; i < WIN; i += 256) imp_s[i] = d_imp[r*WIN + i];
    if (tid == 0) res_s[0] = 0.0f;
    for (int i = tid; i < 3072; i += 256) {
        int gi = T0 - 2047 + i;
        res_s[1 + i] = (gi >= 0) ? d_res[re*NS + gi] : 0.0f;
    }
    __syncthreads();

    float ninv = d_ninv[re];
    int t0l  = tid * 4;
    int base = 2048 + t0l;                         // res[n-j] at res_s[base+k-j]
    float4 wv = *reinterpret_cast<const float4*>(&res_s[base]);   // w0..w3 (aligned)
    float w0 = wv.x, w1 = wv.y, w2 = wv.z, w3 = wv.w;
    float a0 = 0.f, a1 = 0.f, a2 = 0.f, a3 = 0.f;
    #pragma unroll 4
    for (int j = 0; j < WIN; j += 4) {
        float4 iv = *reinterpret_cast<const float4*>(&imp_s[j]);        // broadcast
        float4 rv = *reinterpret_cast<const float4*>(&res_s[base-j-4]); // next window
        // j+0
        a0 = fmaf(iv.x, w0, a0); a1 = fmaf(iv.x, w1, a1);
        a2 = fmaf(iv.x, w2, a2); a3 = fmaf(iv.x, w3, a3);
        // j+1 (v1 = res_s[base-j-1] = rv.w)
        a0 = fmaf(iv.y, rv.w, a0); a1 = fmaf(iv.y, w0, a1);
        a2 = fmaf(iv.y, w1, a2);   a3 = fmaf(iv.y, w2, a3);
        // j+2 (v2 = rv.z)
        a0 = fmaf(iv.z, rv.z, a0); a1 = fmaf(iv.z, rv.w, a1);
        a2 = fmaf(iv.z, w0, a2);   a3 = fmaf(iv.z, w1, a3);
        // j+3 (v3 = rv.y)
        a0 = fmaf(iv.w, rv.y, a0); a1 = fmaf(iv.w, rv.z, a1);
        a2 = fmaf(iv.w, rv.w, a2); a3 = fmaf(iv.w, w0, a3);
        // rotate window down by 4
        w0 = rv.x; w1 = rv.y; w2 = rv.z; w3 = rv.w;
    }
    float4 ov = make_float4(a0*ninv, a1*ninv, a2*ninv, a3*ninv);
    *reinterpret_cast<float4*>(gout + t0l) = ov;
}

// ------- K5: modal prefactors  P_o = ninv * A_o * sum_j imp[j] e^{s(2047-j)D}
__global__ void __launch_bounds__(256) k_pref()
{
    int w   = blockIdx.x;            // mode 0..511
    int tid = threadIdx.x;
    int re  = w & 31;
    int r   = re >> 1;

    __shared__ float sb12, sbrest, sstepc, ssteps;
    if (tid == 0) {
        double beta_d = (double)d_om[w] * (10.0 / 65535.0);
        float b12 = __int_as_float(__float_as_int((float)beta_d) & 0xFFFFF000u);
        sb12   = b12;
        sbrest = (float)(beta_d - (double)b12);
        sstepc = (float)cos(beta_d);
        ssteps = (float)sin(beta_d);
    }
    __syncthreads();

    float xd = d_xd[w];
    float b12 = sb12, brest = sbrest, stepc = sstepc, steps = ssteps;

    const double TPd = 6.283185307179586476925287;
    const float  TPH = 6.28125f;
    const float  TPM = (float)(TPd - (double)TPH);
    const float  TPL = (float)(TPd - (double)TPH - (double)(float)(TPd - (double)TPH));
    const float  INV2PI = 0.15915494309189535f;

    int   k0 = tid * 8;
    float kf = (float)k0;
    float phi0 = kf * b12;                        // exact (8+12 mantissa bits)
    float q  = rintf(phi0 * INV2PI);
    float rp = fmaf(-q, TPH, phi0);               // q*TPH exact
    rp = fmaf(-q, TPM, rp);
    rp = fmaf(-q, TPL, rp);
    rp = fmaf(kf, brest, rp);
    float c, s;
    sincosf(rp, &s, &c);
    float env = expf(-xd * (kf * DELTA));
    float ef  = expf(-xd * DELTA);

    const float* impr = d_imp + r*WIN + (2047 - k0);
    float fr = 0.f, fi = 0.f;
    #pragma unroll
    for (int j = 0; j < 8; ++j) {
        float wgt = impr[-j] * env;
        fr = fmaf(wgt, c, fr);
        fi = fmaf(wgt, s, fi);
        float c2 = c*stepc - s*steps;             // rotate by beta
        float s2 = c*steps + s*stepc;
        c = c2; s = s2;
        env *= ef;
    }

    double sr = (double)fr, si = (double)fi;
    #pragma unroll
    for (int off = 16; off; off >>= 1) {
        sr += __shfl_down_sync(0xffffffffu, sr, off);
        si += __shfl_down_sync(0xffffffffu, si, off);
    }
    __shared__ double redr[8], redi[8];
    int wi = tid >> 5, lane = tid & 31;
    if (lane == 0) { redr[wi] = sr; redi[wi] = si; }
    __syncthreads();
    if (tid == 0) {
        double Sr = 0.0, Si = 0.0;
        #pragma unroll
        for (int i = 0; i < 8; ++i) { Sr += redr[i]; Si += redi[i]; }
        float phi = d_phi[w];
        float a   = d_aa[w], am = d_am[w];
        float cp = cosf(phi), sp = sinf(phi);
        float Ar =  a * am * cp;
        float Ai = -a * am * sp;          // A = a*amp^2 * e^{-i phi}
        float ninv = d_ninv[re];
        float Cr = (float)Sr, Ci = (float)Si;
        d_Pr[w] = (Ar*Cr - Ai*Ci) * ninv;
        d_Pi[w] = (Ar*Ci + Ai*Cr) * ninv;
    }
}

// -------------- K6: modal tail of g — 32 samples/thread, phasor rotation ----
// smem load + barrier happen BEFORE any early exit (R10 lesson).
__global__ void __launch_bounds__(256) k_gmod()
{
    int re  = blockIdx.y;
    int tid = threadIdx.x;
    int T0  = HEAD + blockIdx.x * 8192;
    int n0  = T0 + tid * 32;

    __shared__ float sxd[NOSC], som[NOSC], spr[NOSC], spi[NOSC];
    __shared__ float ssc[NOSC], ssn[NOSC], sed[NOSC];
    __shared__ int   sgc[NOSC];
    if (tid < NOSC) {
        int idx = tid * RE + re;
        sxd[tid] = d_xd[idx]; som[tid] = d_om[idx];
        spr[tid] = d_Pr[idx]; spi[tid] = d_Pi[idx];
        ssc[tid] = d_sc[idx]; ssn[tid] = d_sn[idx]; sed[tid] = d_ed[idx];
        sgc[tid] = d_nco[idx] + WIN;     // per-mode g support
    }
    __syncthreads();

    if (n0 >= NS) return;
    int Lg  = d_Lg[re];
    float* gp = d_g + re*NS + n0;

    if (n0 >= Lg) {                      // g numerically zero here
        #pragma unroll
        for (int j = 0; j < 32; j += 4)
            *reinterpret_cast<float4*>(gp + j) = make_float4(0.f, 0.f, 0.f, 0.f);
        return;
    }

    float acc[32];
    #pragma unroll
    for (int j = 0; j < 32; ++j) acc[j] = 0.f;

    float tau0 = __fmul_rn((float)(n0 - 2047), DELTA);
    #pragma unroll
    for (int o = 0; o < NOSC; ++o) {
        if (n0 < sgc[o]) {               // skip fully-negligible modes
            float s, c;
            sincosf(som[o] * tau0, &s, &c);
            float env = expf(-sxd[o] * tau0);
            float pr = spr[o], pi = spi[o];
            float sc = ssc[o], sn = ssn[o], ed = sed[o];
            #pragma unroll
            for (int j = 0; j < 32; ++j) {
                acc[j] = fmaf(env, pr*c - pi*s, acc[j]);
                float c2 = c*sc - s*sn;  // rotate phase by beta
                float s2 = c*sn + s*sc;
                c = c2; s = s2;
                env *= ed;               // advance envelope
            }
        }
    }
    #pragma unroll
    for (int j = 0; j < 32; j += 4)
        *reinterpret_cast<float4*>(gp + j) = make_float4(acc[j], acc[j+1], acc[j+2], acc[j+3]);
}

// ------------------ K7: routed_c (16-tap sparse convolution) -----------------
__global__ void __launch_bounds__(256) k_rc()
{
    int c = blockIdx.y;
    int n = blockIdx.x * 256 + threadIdx.x;
    int fhi = n >> 7;
    int flo = max(0, (n - (WIN - 1) + 127) >> 7);
    const float* rt = d_routed + c*FRAMES;
    const float* im = d_imp    + c*WIN;
    float acc = 0.0f;
    for (int f = flo; f <= fhi; ++f)
        acc = fmaf(rt[f], im[n - (f << 7)], acc);
    d_rc[c*NS + n] = acc;
}

// -------- K8: conv-apply (sparse taps on g), deform mix, res mix, tanh -------
__global__ void __launch_bounds__(256) k_conv()
{
    int r  = blockIdx.y;
    int N0 = blockIdx.x * 512;
    int tid = threadIdx.x;

    __shared__ float rt_s[FRAMES];
    for (int i = tid; i < FRAMES; i += 256) rt_s[i] = d_routed[r*FRAMES + i];
    __syncthreads();

    const float* g0 = d_g + (2*r)*NS;
    const float* g1 = g0 + NS;
    int LgM = max(d_Lg[2*r], d_Lg[2*r + 1]);
    float m0v = d_m0[r], m1v = d_m1[r], gav = d_ga[r];

    #pragma unroll
    for (int h = 0; h < 2; ++h) {
        int n = N0 + tid + h*256;
        float cpos = __fsub_rn(__fmul_rn((float)n + 0.5f, 1.0f/256.0f), 0.5f);
        float fl = floorf(cpos);
        int   i0 = (int)fl;
        float w  = cpos - fl;
        int k0 = max(i0, 0);
        int k1 = min(i0 + 1, DEFF - 1);
        float w0 = 1.0f - w;
        float dv0 = __fadd_rn(__fmul_rn(w0, d_dsm[k0]),        __fmul_rn(w, d_dsm[k1]));
        float dv1 = __fadd_rn(__fmul_rn(w0, d_dsm[DEFF + k0]), __fmul_rn(w, d_dsm[DEFF + k1]));

        int fhi = n >> 7;
        int flo = max(0, (n - LgM + 128) >> 7);
        float c0 = 0.f, c1 = 0.f;
        for (int f = flo; f <= fhi; ++f) {
            float rf = rt_s[f];
            int k = n - (f << 7);
            c0 = fmaf(rf, __ldg(g0 + k), c0);
            c1 = fmaf(rf, __ldg(g1 + k), c1);
        }
        float x  = __fadd_rn(__fmul_rn(dv0, c0), __fmul_rn(dv1, c1));
        float rc = d_rc[r*NS + n];
        float x2 = __fadd_rn(__fmul_rn(m0v, rc), __fmul_rn(m1v, x));
        d_xv[r*NS + n] = tanhf(__fmul_rn(x2, gav));
    }
}

// -------------------- K9: final reductions over res / cpd --------------------
__global__ void __launch_bounds__(256) k_out(float* __restrict__ out, int out_size)
{
    int n = blockIdx.x * 256 + threadIdx.x;
    float s = 0.0f;
    #pragma unroll
    for (int r = 0; r < NRES; ++r) s = __fadd_rn(s, d_xv[r*NS + n]);
    float cs = 0.0f;
    #pragma unroll
    for (int c = 0; c < NCPD; ++c) cs = __fadd_rn(cs, d_rc[c*NS + n]);
    out[n] = s;
    if (OC + n < out_size) out[OC + n] = cs;
}

// ------------------------------------------------------------------------------
extern "C" void kernel_launch(void* const* d_in, const int* in_sizes, int n_in,
                              void* d_out, int out_size)
{
    const float* ctrl    = (const float*)d_in[0];
    const float* defo    = (const float*)d_in[1];
    const float* noise   = (const float*)d_in[2];
    const float* attack  = (const float*)d_in[3];
    const float* router  = (const float*)d_in[4];
    const float* mixp    = (const float*)d_in[5];
    const float* gains   = (const float*)d_in[6];
    const float* damping = (const float*)d_in[7];
    const float* mass    = (const float*)d_in[8];
    const float* tension = (const float*)d_in[9];
    const float* idisp   = (const float*)d_in[10];
    const float* amps    = (const float*)d_in[11];
    float* out = (float*)d_out;

    k_setup<<<82, 512>>>(ctrl, defo, noise, attack, router, mixp, gains,
                         damping, mass, tension, idisp, amps, out, out_size);
    k_res  <<<dim3(256, RE),   256>>>();
    k_norm <<<RE,              256>>>();
    k_gfir <<<dim3(HEAD/1024, RE), 256>>>();   // 4th launch -> ncu capture slot
    k_pref <<<ORE,             256>>>();       // needs only norm/setup; after gfir OK
    k_gmod <<<dim3(8, RE),     256>>>();
    k_rc   <<<dim3(256, NCPD), 256>>>();
    k_conv <<<dim3(128, NRES), 256>>>();
    k_out  <<<256,             256>>>(out, out_size);
}